// round 4
// baseline (speedup 1.0000x reference)
#include <cuda_runtime.h>
#include <cstdint>

#define N_NODES_MAX 250000

// Scratch (device globals — no allocation allowed)
__device__ float  g_deg  [N_NODES_MAX];
__device__ float  g_dinv [N_NODES_MAX];
__device__ float4 g_xsr  [N_NODES_MAX * 2];  // raw x * dinv, 32B/node (5 of 8 floats used)
__device__ float4 g_agg1 [N_NODES_MAX * 2];  // layer-1 raw aggregation
__device__ float4 g_xs2  [N_NODES_MAX];      // layer-2 scaled features (16B/node)

__device__ __forceinline__ void red_add_v4(float4* addr, float4 v) {
    unsigned long long ga = __cvta_generic_to_global(addr);
    asm volatile("red.global.add.v4.f32 [%0], {%1,%2,%3,%4};"
                 :: "l"(ga), "f"(v.x), "f"(v.y), "f"(v.z), "f"(v.w)
                 : "memory");
}
__device__ __forceinline__ void red_add_f32(float* addr, float v) {
    unsigned long long ga = __cvta_generic_to_global(addr);
    asm volatile("red.global.add.f32 [%0], %1;" :: "l"(ga), "f"(v) : "memory");
}

// ---------------- kernels ----------------

__global__ void k_deg_init(int n) {
    int i = blockIdx.x * blockDim.x + threadIdx.x;
    if (i < n) g_deg[i] = 1.0f;   // self-loop
}

// 8 edges per thread via 2x int4
__global__ void k_deg_count(const int4* __restrict__ dst4, int e4) {
    int i = (blockIdx.x * blockDim.x + threadIdx.x) * 2;
    if (i < e4) {
        int4 d0 = dst4[i];
        atomicAdd(&g_deg[d0.x], 1.0f);
        atomicAdd(&g_deg[d0.y], 1.0f);
        atomicAdd(&g_deg[d0.z], 1.0f);
        atomicAdd(&g_deg[d0.w], 1.0f);
        if (i + 1 < e4) {
            int4 d1 = dst4[i + 1];
            atomicAdd(&g_deg[d1.x], 1.0f);
            atomicAdd(&g_deg[d1.y], 1.0f);
            atomicAdd(&g_deg[d1.z], 1.0f);
            atomicAdd(&g_deg[d1.w], 1.0f);
        }
    }
}
__global__ void k_deg_tail(const int* __restrict__ dst, int start, int e) {
    int i = start + blockIdx.x * blockDim.x + threadIdx.x;
    if (i < e) atomicAdd(&g_deg[dst[i]], 1.0f);
}

// dinv = rsqrt(deg); xsr = x*dinv (5 floats, padded); agg1 init = xsr (self loop)
__global__ void k_node1(const float* __restrict__ x, int n) {
    int i = blockIdx.x * blockDim.x + threadIdx.x;
    if (i >= n) return;
    float dinv = rsqrtf(g_deg[i]);
    g_dinv[i] = dinv;
    float4 a;
    a.x = x[i * 5 + 0] * dinv;
    a.y = x[i * 5 + 1] * dinv;
    a.z = x[i * 5 + 2] * dinv;
    a.w = x[i * 5 + 3] * dinv;
    float4 b;
    b.x = x[i * 5 + 4] * dinv;
    b.y = 0.f; b.z = 0.f; b.w = 0.f;
    g_xsr [i * 2]     = a;
    g_xsr [i * 2 + 1] = b;
    g_agg1[i * 2]     = a;
    g_agg1[i * 2 + 1] = b;
}

// layer-1 aggregation over raw 5-dim features; 2 edges/thread, int2 idx
__global__ void k_edge1(const int2* __restrict__ src2,
                        const int2* __restrict__ dst2, int e2) {
    int i = blockIdx.x * blockDim.x + threadIdx.x;
    if (i >= e2) return;
    int2 s = src2[i];
    int2 d = dst2[i];
    // both gathers in flight before REDs (MLP)
    float4 a0 = __ldg(&g_xsr[s.x * 2]);
    float4 a1 = __ldg(&g_xsr[s.y * 2]);
    float  b0 = __ldg(&g_xsr[s.x * 2 + 1].x);
    float  b1 = __ldg(&g_xsr[s.y * 2 + 1].x);
    red_add_v4 (&g_agg1[d.x * 2], a0);
    red_add_f32(&g_agg1[d.x * 2 + 1].x, b0);
    red_add_v4 (&g_agg1[d.y * 2], a1);
    red_add_f32(&g_agg1[d.y * 2 + 1].x, b1);
}

// h = relu(dinv*(agg1raw @ W1) + b1); xs2 = (h @ W2)*dinv; out init = xs2 (self loop)
__global__ void k_node2(const float* __restrict__ W1,
                        const float* __restrict__ b1,
                        const float* __restrict__ W2,
                        float4* __restrict__ out, int n) {
    int i = blockIdx.x * blockDim.x + threadIdx.x;
    if (i >= n) return;
    float dinv = g_dinv[i];
    float4 a = g_agg1[i * 2];
    float4 bq = g_agg1[i * 2 + 1];
    float xa[5] = {a.x, a.y, a.z, a.w, bq.x};
    float h[16];
#pragma unroll
    for (int j = 0; j < 16; j++) {
        float acc = 0.f;
#pragma unroll
        for (int k = 0; k < 5; k++) acc = fmaf(xa[k], W1[k * 16 + j], acc);
        h[j] = fmaxf(fmaf(dinv, acc, b1[j]), 0.f);
    }
    float4 v;
    float* vp = &v.x;
#pragma unroll
    for (int c = 0; c < 4; c++) {
        float acc = 0.f;
#pragma unroll
        for (int j = 0; j < 16; j++) acc = fmaf(h[j], W2[j * 4 + c], acc);
        vp[c] = acc * dinv;
    }
    g_xs2[i] = v;
    out[i]   = v;
}

// layer-2 aggregation; 2 edges/thread, int2 idx
__global__ void k_edge2(const int2* __restrict__ src2,
                        const int2* __restrict__ dst2,
                        float4* __restrict__ out, int e2) {
    int i = blockIdx.x * blockDim.x + threadIdx.x;
    if (i >= e2) return;
    int2 s = src2[i];
    int2 d = dst2[i];
    float4 v0 = __ldg(&g_xs2[s.x]);
    float4 v1 = __ldg(&g_xs2[s.y]);
    red_add_v4(&out[d.x], v0);
    red_add_v4(&out[d.y], v1);
}

__global__ void k_edge_tail(const int* __restrict__ src,
                            const int* __restrict__ dst,
                            float4* __restrict__ out, int start, int e, int layer) {
    int i = start + blockIdx.x * blockDim.x + threadIdx.x;
    if (i >= e) return;
    int s = src[i], d = dst[i];
    if (layer == 1) {
        float4 a = g_xsr[s * 2];
        float  b = g_xsr[s * 2 + 1].x;
        red_add_v4 (&g_agg1[d * 2], a);
        red_add_f32(&g_agg1[d * 2 + 1].x, b);
    } else {
        red_add_v4(&out[d], g_xs2[s]);
    }
}

__global__ void k_node3(const float* __restrict__ b2,
                        float4* __restrict__ out, int n) {
    int i = blockIdx.x * blockDim.x + threadIdx.x;
    if (i >= n) return;
    float dinv = g_dinv[i];
    float4 v = out[i];
    v.x = fmaxf(fmaf(dinv, v.x, b2[0]), 0.f);
    v.y = fmaxf(fmaf(dinv, v.y, b2[1]), 0.f);
    v.z = fmaxf(fmaf(dinv, v.z, b2[2]), 0.f);
    v.w = fmaxf(fmaf(dinv, v.w, b2[3]), 0.f);
    out[i] = v;
}

// ---------------- launch ----------------

extern "C" void kernel_launch(void* const* d_in, const int* in_sizes, int n_in,
                              void* d_out, int out_size) {
    const float* x  = (const float*)d_in[0];   // [N,5]
    const int*   ei = (const int*)d_in[1];     // [2,E] int32
    const float* W1 = (const float*)d_in[2];   // [5,16]
    const float* b1 = (const float*)d_in[3];   // [16]
    const float* W2 = (const float*)d_in[4];   // [16,4]
    const float* b2 = (const float*)d_in[5];   // [4]

    int n = in_sizes[0] / 5;
    int e = in_sizes[1] / 2;
    const int* src = ei;
    const int* dst = ei + e;

    float4* out = (float4*)d_out;

    const int BT = 256;
    int gn = (n + BT - 1) / BT;

    int e2 = e / 2;               // int2-pair count
    int ge2 = (e2 + BT - 1) / BT;
    int e4 = e / 4;               // int4 count for deg
    int gd = ((e4 + 1) / 2 + BT - 1) / BT;
    int etail = e2 * 2;           // first un-paired edge (e even -> etail == e)

    k_deg_init <<<gn, BT>>>(n);
    k_deg_count<<<gd, BT>>>((const int4*)dst, e4);
    if (e4 * 4 < e)
        k_deg_tail<<<1, BT>>>(dst, e4 * 4, e);
    k_node1    <<<gn, BT>>>(x, n);
    k_edge1    <<<ge2, BT>>>((const int2*)src, (const int2*)dst, e2);
    if (etail < e)
        k_edge_tail<<<1, BT>>>(src, dst, out, etail, e, 1);
    k_node2    <<<gn, BT>>>(W1, b1, W2, out, n);
    k_edge2    <<<ge2, BT>>>((const int2*)src, (const int2*)dst, out, e2);
    if (etail < e)
        k_edge_tail<<<1, BT>>>(src, dst, out, etail, e, 2);
    k_node3    <<<gn, BT>>>(b2, out, n);
}

// round 5
// speedup vs baseline: 1.0187x; 1.0187x over previous
#include <cuda_runtime.h>
#include <cstdint>

#define N_NODES_MAX 250000

// Scratch (device globals — zero-initialized at module load; no allocation allowed)
__device__ float  g_deg  [N_NODES_MAX];      // self-resetting: always 0 on kernel_launch entry
__device__ float  g_dinv [N_NODES_MAX];
__device__ float4 g_xsr  [N_NODES_MAX * 2];  // raw x * dinv, 32B/node (5 of 8 floats used)
__device__ float4 g_agg1 [N_NODES_MAX * 2];  // layer-1 raw aggregation
__device__ float4 g_xs2  [N_NODES_MAX];      // layer-2 scaled features (16B/node)

__device__ __forceinline__ void red_add_v4(float4* addr, float4 v) {
    unsigned long long ga = __cvta_generic_to_global(addr);
    asm volatile("red.global.add.v4.f32 [%0], {%1,%2,%3,%4};"
                 :: "l"(ga), "f"(v.x), "f"(v.y), "f"(v.z), "f"(v.w)
                 : "memory");
}
__device__ __forceinline__ void red_add_f32(float* addr, float v) {
    unsigned long long ga = __cvta_generic_to_global(addr);
    asm volatile("red.global.add.f32 [%0], %1;" :: "l"(ga), "f"(v) : "memory");
}
__device__ __forceinline__ void pdl_trigger() {
    asm volatile("griddepcontrol.launch_dependents;");
}
__device__ __forceinline__ void pdl_wait() {
    asm volatile("griddepcontrol.wait;" ::: "memory");
}

// ---------------- kernels ----------------

// 8 edges per thread via 2x int4 (first kernel: no wait needed)
__global__ void k_deg_count(const int4* __restrict__ dst4, int e4) {
    pdl_trigger();
    int i = (blockIdx.x * blockDim.x + threadIdx.x) * 2;
    if (i < e4) {
        int4 d0 = dst4[i];
        atomicAdd(&g_deg[d0.x], 1.0f);
        atomicAdd(&g_deg[d0.y], 1.0f);
        atomicAdd(&g_deg[d0.z], 1.0f);
        atomicAdd(&g_deg[d0.w], 1.0f);
        if (i + 1 < e4) {
            int4 d1 = dst4[i + 1];
            atomicAdd(&g_deg[d1.x], 1.0f);
            atomicAdd(&g_deg[d1.y], 1.0f);
            atomicAdd(&g_deg[d1.z], 1.0f);
            atomicAdd(&g_deg[d1.w], 1.0f);
        }
    }
}
__global__ void k_deg_tail(const int* __restrict__ dst, int start, int e) {
    pdl_trigger();
    int i = start + blockIdx.x * blockDim.x + threadIdx.x;
    if (i < e) atomicAdd(&g_deg[dst[i]], 1.0f);
}

// dinv = rsqrt(deg+1); xsr = x*dinv (5 floats, padded); agg1 init = xsr (self loop); reset deg
__global__ void k_node1(const float* __restrict__ x, int n) {
    pdl_trigger();
    int i = blockIdx.x * blockDim.x + threadIdx.x;
    if (i >= n) return;
    // independent prefetch: x
    float x0 = x[i * 5 + 0], x1 = x[i * 5 + 1], x2 = x[i * 5 + 2],
          x3 = x[i * 5 + 3], x4 = x[i * 5 + 4];
    pdl_wait();   // deg counts complete
    float dinv = rsqrtf(g_deg[i] + 1.0f);   // +1 = self-loop
    g_deg[i] = 0.f;                          // reset for next graph replay
    g_dinv[i] = dinv;
    float4 a = make_float4(x0 * dinv, x1 * dinv, x2 * dinv, x3 * dinv);
    float4 b = make_float4(x4 * dinv, 0.f, 0.f, 0.f);
    g_xsr [i * 2]     = a;
    g_xsr [i * 2 + 1] = b;
    g_agg1[i * 2]     = a;
    g_agg1[i * 2 + 1] = b;
}

// layer-1 aggregation over raw 5-dim features; 2 edges/thread, int2 idx
__global__ void k_edge1(const int2* __restrict__ src2,
                        const int2* __restrict__ dst2, int e2) {
    pdl_trigger();
    int i = blockIdx.x * blockDim.x + threadIdx.x;
    if (i >= e2) return;
    int2 s = src2[i];   // independent prefetch (idx arrays are kernel inputs)
    int2 d = dst2[i];
    pdl_wait();         // g_xsr / g_agg1 ready
    float4 a0 = __ldg(&g_xsr[s.x * 2]);
    float4 a1 = __ldg(&g_xsr[s.y * 2]);
    float  b0 = __ldg(&g_xsr[s.x * 2 + 1].x);
    float  b1 = __ldg(&g_xsr[s.y * 2 + 1].x);
    red_add_v4 (&g_agg1[d.x * 2], a0);
    red_add_f32(&g_agg1[d.x * 2 + 1].x, b0);
    red_add_v4 (&g_agg1[d.y * 2], a1);
    red_add_f32(&g_agg1[d.y * 2 + 1].x, b1);
}
__global__ void k_edge1_tail(const int* __restrict__ src,
                             const int* __restrict__ dst, int start, int e) {
    pdl_trigger();
    int i = start + blockIdx.x * blockDim.x + threadIdx.x;
    if (i >= e) return;
    int s = src[i], d = dst[i];
    pdl_wait();
    float4 a = g_xsr[s * 2];
    float  b = g_xsr[s * 2 + 1].x;
    red_add_v4 (&g_agg1[d * 2], a);
    red_add_f32(&g_agg1[d * 2 + 1].x, b);
}

// h = relu(dinv*(agg1raw @ W1) + b1); xs2 = (h @ W2)*dinv; out init = xs2 (self loop)
__global__ void k_node2(const float* __restrict__ W1,
                        const float* __restrict__ b1,
                        const float* __restrict__ W2,
                        float4* __restrict__ out, int n) {
    pdl_trigger();
    int i = blockIdx.x * blockDim.x + threadIdx.x;
    if (i >= n) return;
    // independent prefetch: weights (tiny, L2-resident after first warp)
    float w1[5][16], bb1[16], w2[16][4];
#pragma unroll
    for (int k = 0; k < 5; k++)
#pragma unroll
        for (int j = 0; j < 16; j++) w1[k][j] = W1[k * 16 + j];
#pragma unroll
    for (int j = 0; j < 16; j++) bb1[j] = b1[j];
#pragma unroll
    for (int j = 0; j < 16; j++)
#pragma unroll
        for (int c = 0; c < 4; c++) w2[j][c] = W2[j * 4 + c];
    pdl_wait();   // agg1 complete
    float dinv = g_dinv[i];
    float4 a  = g_agg1[i * 2];
    float4 bq = g_agg1[i * 2 + 1];
    float xa[5] = {a.x, a.y, a.z, a.w, bq.x};
    float h[16];
#pragma unroll
    for (int j = 0; j < 16; j++) {
        float acc = 0.f;
#pragma unroll
        for (int k = 0; k < 5; k++) acc = fmaf(xa[k], w1[k][j], acc);
        h[j] = fmaxf(fmaf(dinv, acc, bb1[j]), 0.f);
    }
    float4 v;
    float* vp = &v.x;
#pragma unroll
    for (int c = 0; c < 4; c++) {
        float acc = 0.f;
#pragma unroll
        for (int j = 0; j < 16; j++) acc = fmaf(h[j], w2[j][c], acc);
        vp[c] = acc * dinv;
    }
    g_xs2[i] = v;
    out[i]   = v;
}

// layer-2 aggregation; 2 edges/thread, int2 idx
__global__ void k_edge2(const int2* __restrict__ src2,
                        const int2* __restrict__ dst2,
                        float4* __restrict__ out, int e2) {
    pdl_trigger();
    int i = blockIdx.x * blockDim.x + threadIdx.x;
    if (i >= e2) return;
    int2 s = src2[i];
    int2 d = dst2[i];
    pdl_wait();   // g_xs2 / out init complete
    float4 v0 = __ldg(&g_xs2[s.x]);
    float4 v1 = __ldg(&g_xs2[s.y]);
    red_add_v4(&out[d.x], v0);
    red_add_v4(&out[d.y], v1);
}
__global__ void k_edge2_tail(const int* __restrict__ src,
                             const int* __restrict__ dst,
                             float4* __restrict__ out, int start, int e) {
    pdl_trigger();
    int i = start + blockIdx.x * blockDim.x + threadIdx.x;
    if (i >= e) return;
    int s = src[i], d = dst[i];
    pdl_wait();
    red_add_v4(&out[d], g_xs2[s]);
}

__global__ void k_node3(const float* __restrict__ b2,
                        float4* __restrict__ out, int n) {
    int i = blockIdx.x * blockDim.x + threadIdx.x;
    if (i >= n) return;
    float c0 = b2[0], c1 = b2[1], c2 = b2[2], c3 = b2[3];
    pdl_wait();   // edge2 REDs complete
    float dinv = g_dinv[i];
    float4 v = out[i];
    v.x = fmaxf(fmaf(dinv, v.x, c0), 0.f);
    v.y = fmaxf(fmaf(dinv, v.y, c1), 0.f);
    v.z = fmaxf(fmaf(dinv, v.z, c2), 0.f);
    v.w = fmaxf(fmaf(dinv, v.w, c3), 0.f);
    out[i] = v;
}

// ---------------- launch ----------------

static void launch_k(const void* fn, int grid, int block, void** args, bool pdl) {
    cudaLaunchConfig_t cfg = {};
    cfg.gridDim  = dim3((unsigned)grid, 1, 1);
    cfg.blockDim = dim3((unsigned)block, 1, 1);
    cfg.stream   = 0;
    cudaLaunchAttribute attr;
    attr.id = cudaLaunchAttributeProgrammaticStreamSerialization;
    attr.val.programmaticStreamSerializationAllowed = 1;
    if (pdl) { cfg.attrs = &attr; cfg.numAttrs = 1; }
    cudaLaunchKernelExC(&cfg, fn, args);
}

extern "C" void kernel_launch(void* const* d_in, const int* in_sizes, int n_in,
                              void* d_out, int out_size) {
    const float* x  = (const float*)d_in[0];   // [N,5]
    const int*   ei = (const int*)d_in[1];     // [2,E] int32
    const float* W1 = (const float*)d_in[2];   // [5,16]
    const float* b1 = (const float*)d_in[3];   // [16]
    const float* W2 = (const float*)d_in[4];   // [16,4]
    const float* b2 = (const float*)d_in[5];   // [4]

    int n = in_sizes[0] / 5;
    int e = in_sizes[1] / 2;
    const int* src = ei;
    const int* dst = ei + e;

    float4* out = (float4*)d_out;

    const int BT = 256;
    int gn  = (n + BT - 1) / BT;
    int e2  = e / 2;
    int ge2 = (e2 + BT - 1) / BT;
    int e4  = e / 4;
    int gd  = ((e4 + 1) / 2 + BT - 1) / BT;
    int etail = e2 * 2;
    int dtail = e4 * 4;

    const int2* src2 = (const int2*)src;
    const int2* dst2 = (const int2*)dst;
    const int4* dst4 = (const int4*)dst;

    {   void* a[] = {(void*)&dst4, (void*)&e4};
        launch_k((const void*)k_deg_count, gd, BT, a, false); }
    if (dtail < e) {
        void* a[] = {(void*)&dst, (void*)&dtail, (void*)&e};
        launch_k((const void*)k_deg_tail, 1, BT, a, false); }
    {   void* a[] = {(void*)&x, (void*)&n};
        launch_k((const void*)k_node1, gn, BT, a, true); }
    {   void* a[] = {(void*)&src2, (void*)&dst2, (void*)&e2};
        launch_k((const void*)k_edge1, ge2, BT, a, true); }
    if (etail < e) {
        void* a[] = {(void*)&src, (void*)&dst, (void*)&etail, (void*)&e};
        launch_k((const void*)k_edge1_tail, 1, BT, a, true); }
    {   void* a[] = {(void*)&W1, (void*)&b1, (void*)&W2, (void*)&out, (void*)&n};
        launch_k((const void*)k_node2, gn, BT, a, true); }
    {   void* a[] = {(void*)&src2, (void*)&dst2, (void*)&out, (void*)&e2};
        launch_k((const void*)k_edge2, ge2, BT, a, true); }
    if (etail < e) {
        void* a[] = {(void*)&src, (void*)&dst, (void*)&out, (void*)&etail, (void*)&e};
        launch_k((const void*)k_edge2_tail, 1, BT, a, true); }
    {   void* a[] = {(void*)&b2, (void*)&out, (void*)&n};
        launch_k((const void*)k_node3, gn, BT, a, true); }
}